// round 2
// baseline (speedup 1.0000x reference)
#include <cuda_runtime.h>
#include <cuda_bf16.h>

// Problem constants (GATLayer): V=100000, E=1600000, Fin=128, H=4, Cout=32
#define FIN   128
#define HC    128   // H*Cout
#define NHEAD 4
#define MAXV  100000
#define MAXE  1600000

// -------- scratch (static device globals; allocation-free rule) --------
__device__ __align__(16) float g_z[MAXV * HC];        // 51.2 MB
__device__ __align__(16) float g_ssrc[MAXV * NHEAD];
__device__ __align__(16) float g_sdst[MAXV * NHEAD];
__device__ __align__(16) float g_max[MAXV * NHEAD];
__device__ __align__(16) float g_denom[MAXV * NHEAD];
__device__ __align__(16) int2  g_edge[MAXE];
__device__ int g_is32;

// -------- helpers --------
__device__ __forceinline__ float lrelu(float v) {
    return v >= 0.f ? v : 0.2f * v;
}

// float atomic max via ordered-int trick (valid for all finite floats)
__device__ __forceinline__ void atomicMaxF(float* addr, float v) {
    if (v >= 0.f)
        atomicMax((int*)addr, __float_as_int(v));
    else
        atomicMin((unsigned int*)addr, __float_as_uint(v));
}

__device__ __forceinline__ void red_add_v4(float* addr, float4 v) {
    asm volatile("red.global.add.v4.f32 [%0], {%1,%2,%3,%4};"
                 :: "l"(addr), "f"(v.x), "f"(v.y), "f"(v.z), "f"(v.w)
                 : "memory");
}

// ======================================================================
// Kernel 0a/0b: edge_index dtype probe.
// If data is int64 (values < 2^31), every odd 32-bit word is 0.
// If int32, odd words are real vertex indices (virtually all nonzero).
// We only scan the first min(2E, 256K) words — safe for both layouts.
// ======================================================================
__global__ void flag_reset_kernel() {
    if (threadIdx.x == 0) g_is32 = 0;
}

__global__ void detect_kernel(const unsigned int* __restrict__ w, int n_words) {
    int i = blockIdx.x * blockDim.x + threadIdx.x;
    int j = 2 * i + 1;
    if (j < n_words && w[j] != 0u) g_is32 = 1;
}

// ======================================================================
// Kernel 1: z = x @ W   (fp32 tiled SGEMM, BM=64, BK=32, thread tile 4x8)
// ======================================================================
#define BM 64
#define BK 32
__global__ void gemm_kernel(const float* __restrict__ x,
                            const float* __restrict__ W, int V) {
    __shared__ float Ws[BK][HC];        // 16 KB
    __shared__ float xs[BM][BK + 4];    // 9.2 KB (pad keeps 16B align: 36*4=144)

    int tid = threadIdx.x;
    int tx = tid & 15;     // col group: cols [tx*8, tx*8+8)
    int ty = tid >> 4;     // row group: rows [ty*4, ty*4+4)
    int row0 = blockIdx.x * BM;

    float acc[4][8];
#pragma unroll
    for (int i = 0; i < 4; i++)
#pragma unroll
        for (int j = 0; j < 8; j++) acc[i][j] = 0.f;

    for (int kb = 0; kb < FIN; kb += BK) {
        // load Ws: BK*128 floats = 1024 float4, 4 per thread (coalesced)
#pragma unroll
        for (int i = 0; i < 4; i++) {
            int f = i * 256 + tid;
            int r = f >> 5, c4 = f & 31;
            *(float4*)&Ws[r][c4 * 4] =
                *(const float4*)&W[(kb + r) * HC + c4 * 4];
        }
        // load xs: BM*BK floats = 512 float4, 2 per thread (coalesced)
#pragma unroll
        for (int i = 0; i < 2; i++) {
            int f = i * 256 + tid;
            int r = f >> 3, c4 = f & 7;
            float4 v = make_float4(0.f, 0.f, 0.f, 0.f);
            if (row0 + r < V)
                v = *(const float4*)&x[(size_t)(row0 + r) * FIN + kb + c4 * 4];
            *(float4*)&xs[r][c4 * 4] = v;
        }
        __syncthreads();

#pragma unroll
        for (int k = 0; k < BK; k++) {
            float4 w0 = *(float4*)&Ws[k][tx * 8];
            float4 w1 = *(float4*)&Ws[k][tx * 8 + 4];
#pragma unroll
            for (int i = 0; i < 4; i++) {
                float xv = xs[ty * 4 + i][k];
                acc[i][0] += xv * w0.x; acc[i][1] += xv * w0.y;
                acc[i][2] += xv * w0.z; acc[i][3] += xv * w0.w;
                acc[i][4] += xv * w1.x; acc[i][5] += xv * w1.y;
                acc[i][6] += xv * w1.z; acc[i][7] += xv * w1.w;
            }
        }
        __syncthreads();
    }

#pragma unroll
    for (int i = 0; i < 4; i++) {
        int r = row0 + ty * 4 + i;
        if (r < V) {
            float4 o0 = make_float4(acc[i][0], acc[i][1], acc[i][2], acc[i][3]);
            float4 o1 = make_float4(acc[i][4], acc[i][5], acc[i][6], acc[i][7]);
            *(float4*)&g_z[(size_t)r * HC + tx * 8]     = o0;
            *(float4*)&g_z[(size_t)r * HC + tx * 8 + 4] = o1;
        }
    }
}

// ======================================================================
// Kernel 2: per-vertex attention scores + init max/denom + zero d_out
// thread per (v, h)
// ======================================================================
__global__ void score_kernel(const float* __restrict__ a_src,
                             const float* __restrict__ a_dst,
                             float* __restrict__ out, int V) {
    int idx = blockIdx.x * blockDim.x + threadIdx.x;
    if (idx >= V * NHEAD) return;
    int v = idx >> 2, h = idx & 3;

    const float* zp = g_z + (size_t)v * HC + h * 32;
    const float* as = a_src + h * 32;
    const float* ad = a_dst + h * 32;

    float s = 0.f, d = 0.f;
#pragma unroll
    for (int q = 0; q < 8; q++) {
        float4 zv = *(const float4*)(zp + q * 4);
        float4 av = __ldg((const float4*)(as + q * 4));
        float4 dv = __ldg((const float4*)(ad + q * 4));
        s += zv.x * av.x + zv.y * av.y + zv.z * av.z + zv.w * av.w;
        d += zv.x * dv.x + zv.y * dv.y + zv.z * dv.z + zv.w * dv.w;
    }
    g_ssrc[idx]  = s;
    g_sdst[idx]  = d;
    g_max[idx]   = -1e9f;   // NEG_INIT
    g_denom[idx] = 0.f;

    float4 z4 = make_float4(0.f, 0.f, 0.f, 0.f);
    float* op = out + (size_t)v * HC + h * 32;
#pragma unroll
    for (int q = 0; q < 8; q++) *(float4*)(op + q * 4) = z4;
}

// ======================================================================
// Kernel 3: per-edge segment max (+ convert edge_index to int2)
// ======================================================================
__global__ void max_kernel(const void* __restrict__ ei, int E) {
    int e = blockIdx.x * blockDim.x + threadIdx.x;
    if (e >= E) return;
    int src, dst;
    if (g_is32) {
        const int* p = (const int*)ei;
        src = p[e]; dst = p[E + e];
    } else {
        const long long* p = (const long long*)ei;
        src = (int)p[e]; dst = (int)p[(long long)E + e];
    }
    g_edge[e] = make_int2(src, dst);

    float4 ss = *(const float4*)&g_ssrc[src * 4];
    float4 sd = *(const float4*)&g_sdst[dst * 4];
    atomicMaxF(&g_max[dst * 4 + 0], lrelu(ss.x + sd.x));
    atomicMaxF(&g_max[dst * 4 + 1], lrelu(ss.y + sd.y));
    atomicMaxF(&g_max[dst * 4 + 2], lrelu(ss.z + sd.z));
    atomicMaxF(&g_max[dst * 4 + 3], lrelu(ss.w + sd.w));
}

// ======================================================================
// Kernel 4: per-edge exp-sum into denom
// ======================================================================
__global__ void sum_kernel(int E) {
    int e = blockIdx.x * blockDim.x + threadIdx.x;
    if (e >= E) return;
    int2 ed = g_edge[e];
    float4 ss = *(const float4*)&g_ssrc[ed.x * 4];
    float4 sd = *(const float4*)&g_sdst[ed.y * 4];
    float4 mx = *(const float4*)&g_max[ed.y * 4];
    atomicAdd(&g_denom[ed.y * 4 + 0], __expf(lrelu(ss.x + sd.x) - mx.x));
    atomicAdd(&g_denom[ed.y * 4 + 1], __expf(lrelu(ss.y + sd.y) - mx.y));
    atomicAdd(&g_denom[ed.y * 4 + 2], __expf(lrelu(ss.z + sd.z) - mx.z));
    atomicAdd(&g_denom[ed.y * 4 + 3], __expf(lrelu(ss.w + sd.w) - mx.w));
}

// ======================================================================
// Kernel 5: aggregation — one warp per edge, red.v4 into d_out
// lane l covers channels [4l, 4l+4), head = l>>3
// ======================================================================
__global__ void agg_kernel(float* __restrict__ out, int E) {
    int gw = (blockIdx.x * blockDim.x + threadIdx.x) >> 5;
    int lane = threadIdx.x & 31;
    if (gw >= E) return;

    int2 ed = g_edge[gw];
    int h = lane >> 3;

    float ev = lrelu(g_ssrc[ed.x * 4 + h] + g_sdst[ed.y * 4 + h]);
    float alpha = __expf(ev - g_max[ed.y * 4 + h]) /
                  (g_denom[ed.y * 4 + h] + 1e-9f);

    float4 zv = *(const float4*)&g_z[(size_t)ed.x * HC + lane * 4];
    zv.x *= alpha; zv.y *= alpha; zv.z *= alpha; zv.w *= alpha;
    red_add_v4(&out[(size_t)ed.y * HC + lane * 4], zv);
}

// ======================================================================
// Kernel 6: ELU epilogue in-place
// ======================================================================
__global__ void elu_kernel(float* __restrict__ out, int n4) {
    int i = blockIdx.x * blockDim.x + threadIdx.x;
    if (i >= n4) return;
    float4* p = (float4*)out;
    float4 a = p[i];
    a.x = a.x > 0.f ? a.x : expm1f(a.x);
    a.y = a.y > 0.f ? a.y : expm1f(a.y);
    a.z = a.z > 0.f ? a.z : expm1f(a.z);
    a.w = a.w > 0.f ? a.w : expm1f(a.w);
    p[i] = a;
}

// ======================================================================
extern "C" void kernel_launch(void* const* d_in, const int* in_sizes, int n_in,
                              void* d_out, int out_size) {
    const float* x     = (const float*)d_in[0];
    const void*  ei    = d_in[1];
    const float* W     = (const float*)d_in[2];
    const float* a_src = (const float*)d_in[3];
    const float* a_dst = (const float*)d_in[4];
    float* out = (float*)d_out;

    int V = in_sizes[0] / FIN;
    int E = in_sizes[1] / 2;

    // dtype probe for edge_index (int32 vs int64)
    flag_reset_kernel<<<1, 32>>>();
    int scan_words = 2 * E;
    if (scan_words > 262144) scan_words = 262144;
    int probe_threads = scan_words / 2;
    detect_kernel<<<(probe_threads + 255) / 256, 256>>>(
        (const unsigned int*)ei, scan_words);

    gemm_kernel<<<(V + BM - 1) / BM, 256>>>(x, W, V);
    score_kernel<<<(V * NHEAD + 255) / 256, 256>>>(a_src, a_dst, out, V);
    max_kernel<<<(E + 255) / 256, 256>>>(ei, E);
    sum_kernel<<<(E + 255) / 256, 256>>>(E);
    agg_kernel<<<(E + 7) / 8, 256>>>(out, E);   // 8 warps/block, warp per edge
    elu_kernel<<<(V * (HC / 4) + 255) / 256, 256>>>(out, V * (HC / 4));
}

// round 3
// speedup vs baseline: 1.2259x; 1.2259x over previous
#include <cuda_runtime.h>
#include <cuda_bf16.h>

// Problem constants (GATLayer): V=100000, E=1600000, Fin=128, H=4, Cout=32
#define FIN   128
#define HC    128   // H*Cout
#define NHEAD 4
#define MAXV  100000
#define MAXE  1600000

// -------- scratch (static device globals; allocation-free rule) --------
__device__ __align__(16) float g_z[MAXV * HC];        // 51.2 MB
__device__ __align__(16) float g_ssrc[MAXV * NHEAD];
__device__ __align__(16) float g_sdst[MAXV * NHEAD];
__device__ __align__(16) float g_denom[MAXV * NHEAD];
__device__ __align__(16) int2  g_edge[MAXE];
__device__ int g_is32;

// -------- helpers --------
__device__ __forceinline__ float lrelu(float v) {
    return v >= 0.f ? v : 0.2f * v;
}

__device__ __forceinline__ void red_add_v4(float* addr, float4 v) {
    asm volatile("red.global.add.v4.f32 [%0], {%1,%2,%3,%4};"
                 :: "l"(addr), "f"(v.x), "f"(v.y), "f"(v.z), "f"(v.w)
                 : "memory");
}

__device__ __forceinline__ void red_add_f32(float* addr, float v) {
    asm volatile("red.global.add.f32 [%0], %1;"
                 :: "l"(addr), "f"(v) : "memory");
}

// ======================================================================
// Kernel 0a/0b: edge_index dtype probe.
// If data is int64 (values < 2^31), every odd 32-bit word is 0.
// If int32, odd words are real vertex indices (virtually all nonzero).
// ======================================================================
__global__ void flag_reset_kernel() {
    if (threadIdx.x == 0) g_is32 = 0;
}

__global__ void detect_kernel(const unsigned int* __restrict__ w, int n_words) {
    int i = blockIdx.x * blockDim.x + threadIdx.x;
    int j = 2 * i + 1;
    if (j < n_words && w[j] != 0u) g_is32 = 1;
}

// ======================================================================
// Kernel 1: edge_index -> int2 (coalesced, no atomics)
// ======================================================================
__global__ void convert_kernel(const void* __restrict__ ei, int E) {
    int e = blockIdx.x * blockDim.x + threadIdx.x;
    if (e >= E) return;
    int src, dst;
    if (g_is32) {
        const int* p = (const int*)ei;
        src = p[e]; dst = p[E + e];
    } else {
        const long long* p = (const long long*)ei;
        src = (int)p[e]; dst = (int)p[(long long)E + e];
    }
    g_edge[e] = make_int2(src, dst);
}

// ======================================================================
// Kernel 2: z = x @ W  (fp32 tiled SGEMM, BM=64, BK=32, thread tile 4x8)
// Fused epilogue: per-vertex attention scores s_src/s_dst via 4-lane
// shfl reduction, denom init, out zeroing.
// ======================================================================
#define BM 64
#define BK 32
__global__ void gemm_kernel(const float* __restrict__ x,
                            const float* __restrict__ W,
                            const float* __restrict__ a_src,
                            const float* __restrict__ a_dst,
                            float* __restrict__ out, int V) {
    __shared__ float Ws[BK][HC];        // 16 KB
    __shared__ float xs[BM][BK + 4];

    int tid = threadIdx.x;
    int tx = tid & 15;     // col group: cols [tx*8, tx*8+8)
    int ty = tid >> 4;     // row group: rows [ty*4, ty*4+4)
    int row0 = blockIdx.x * BM;

    // attention vectors for my 8 channels (head h = tx>>2 is fixed per thread)
    float as[8], ad[8];
#pragma unroll
    for (int j = 0; j < 8; j++) {
        as[j] = __ldg(&a_src[tx * 8 + j]);
        ad[j] = __ldg(&a_dst[tx * 8 + j]);
    }

    float acc[4][8];
#pragma unroll
    for (int i = 0; i < 4; i++)
#pragma unroll
        for (int j = 0; j < 8; j++) acc[i][j] = 0.f;

    for (int kb = 0; kb < FIN; kb += BK) {
#pragma unroll
        for (int i = 0; i < 4; i++) {
            int f = i * 256 + tid;
            int r = f >> 5, c4 = f & 31;
            *(float4*)&Ws[r][c4 * 4] =
                *(const float4*)&W[(kb + r) * HC + c4 * 4];
        }
#pragma unroll
        for (int i = 0; i < 2; i++) {
            int f = i * 256 + tid;
            int r = f >> 3, c4 = f & 7;
            float4 v = make_float4(0.f, 0.f, 0.f, 0.f);
            if (row0 + r < V)
                v = *(const float4*)&x[(size_t)(row0 + r) * FIN + kb + c4 * 4];
            *(float4*)&xs[r][c4 * 4] = v;
        }
        __syncthreads();

#pragma unroll
        for (int k = 0; k < BK; k++) {
            float4 w0 = *(float4*)&Ws[k][tx * 8];
            float4 w1 = *(float4*)&Ws[k][tx * 8 + 4];
#pragma unroll
            for (int i = 0; i < 4; i++) {
                float xv = xs[ty * 4 + i][k];
                acc[i][0] += xv * w0.x; acc[i][1] += xv * w0.y;
                acc[i][2] += xv * w0.z; acc[i][3] += xv * w0.w;
                acc[i][4] += xv * w1.x; acc[i][5] += xv * w1.y;
                acc[i][6] += xv * w1.z; acc[i][7] += xv * w1.w;
            }
        }
        __syncthreads();
    }

    // write z + fused per-head score reduction
#pragma unroll
    for (int i = 0; i < 4; i++) {
        int r = row0 + ty * 4 + i;
        float ps = 0.f, pd = 0.f;
#pragma unroll
        for (int j = 0; j < 8; j++) {
            ps += acc[i][j] * as[j];
            pd += acc[i][j] * ad[j];
        }
        // reduce over the 4 consecutive lanes covering one head
        ps += __shfl_xor_sync(0xffffffffu, ps, 1);
        pd += __shfl_xor_sync(0xffffffffu, pd, 1);
        ps += __shfl_xor_sync(0xffffffffu, ps, 2);
        pd += __shfl_xor_sync(0xffffffffu, pd, 2);

        if (r < V) {
            *(float4*)&g_z[(size_t)r * HC + tx * 8] =
                make_float4(acc[i][0], acc[i][1], acc[i][2], acc[i][3]);
            *(float4*)&g_z[(size_t)r * HC + tx * 8 + 4] =
                make_float4(acc[i][4], acc[i][5], acc[i][6], acc[i][7]);
            if ((tx & 3) == 0) {
                int h = tx >> 2;
                g_ssrc[r * 4 + h] = ps;
                g_sdst[r * 4 + h] = pd;
            }
        }
    }

    // zero out rows + denom for this block's row range (64 rows)
    // out: 64*128 floats = 2048 float4 over 256 threads -> 8 each
    float4 z4 = make_float4(0.f, 0.f, 0.f, 0.f);
#pragma unroll
    for (int i = 0; i < 8; i++) {
        int f = i * 256 + tid;          // float4 index within tile
        int r = row0 + (f >> 5);
        if (r < V) *(float4*)&out[(size_t)r * HC + (f & 31) * 4] = z4;
    }
    // denom: 64 rows * 4 heads = 256 floats = 64 float4
    if (tid < 64) {
        int r = row0 + tid;
        if (r < V) *(float4*)&g_denom[r * 4] = z4;
    }
}

// ======================================================================
// Kernel 3: fused edge sweep — one warp per edge.
//   w = exp(lrelu(s_src[src,h] + s_dst[dst,h]))   (no max subtraction;
//   alpha = exp(e-m)/sum exp(e-m) == exp(e)/sum exp(e), e is O(5))
//   denom[dst,h] += w          (scalar red, one lane per head)
//   out[dst,:]  += w * z[src,:] (red.v4, 32 lanes x 4ch)
// ======================================================================
__global__ void edge_kernel(float* __restrict__ out, int E) {
    int gw = (blockIdx.x * blockDim.x + threadIdx.x) >> 5;
    int lane = threadIdx.x & 31;
    if (gw >= E) return;

    int2 ed = g_edge[gw];
    int h = lane >> 3;

    float e = lrelu(g_ssrc[ed.x * 4 + h] + g_sdst[ed.y * 4 + h]);
    float w = __expf(e);

    if ((lane & 7) == 0)
        red_add_f32(&g_denom[ed.y * 4 + h], w);

    float4 zv = *(const float4*)&g_z[(size_t)ed.x * HC + lane * 4];
    zv.x *= w; zv.y *= w; zv.z *= w; zv.w *= w;
    red_add_v4(&out[(size_t)ed.y * HC + lane * 4], zv);
}

// ======================================================================
// Kernel 4: epilogue — divide by denom, ELU, in-place on d_out
// thread per float4; v = i>>5, head = (i>>3)&3
// ======================================================================
__global__ void epilogue_kernel(float* __restrict__ out, int n4) {
    int i = blockIdx.x * blockDim.x + threadIdx.x;
    if (i >= n4) return;
    int v = i >> 5;
    int h = (i >> 3) & 3;
    float inv = 1.f / (g_denom[v * 4 + h] + 1e-9f);
    float4* p = (float4*)out;
    float4 a = p[i];
    a.x *= inv; a.y *= inv; a.z *= inv; a.w *= inv;
    a.x = a.x > 0.f ? a.x : expm1f(a.x);
    a.y = a.y > 0.f ? a.y : expm1f(a.y);
    a.z = a.z > 0.f ? a.z : expm1f(a.z);
    a.w = a.w > 0.f ? a.w : expm1f(a.w);
    p[i] = a;
}

// ======================================================================
extern "C" void kernel_launch(void* const* d_in, const int* in_sizes, int n_in,
                              void* d_out, int out_size) {
    const float* x     = (const float*)d_in[0];
    const void*  ei    = d_in[1];
    const float* W     = (const float*)d_in[2];
    const float* a_src = (const float*)d_in[3];
    const float* a_dst = (const float*)d_in[4];
    float* out = (float*)d_out;

    int V = in_sizes[0] / FIN;
    int E = in_sizes[1] / 2;

    // dtype probe for edge_index (int32 vs int64)
    flag_reset_kernel<<<1, 32>>>();
    int scan_words = 2 * E;
    if (scan_words > 262144) scan_words = 262144;
    int probe_threads = scan_words / 2;
    detect_kernel<<<(probe_threads + 255) / 256, 256>>>(
        (const unsigned int*)ei, scan_words);

    convert_kernel<<<(E + 255) / 256, 256>>>(ei, E);
    gemm_kernel<<<(V + BM - 1) / BM, 256>>>(x, W, a_src, a_dst, out, V);
    edge_kernel<<<(E + 7) / 8, 256>>>(out, E);      // warp per edge
    epilogue_kernel<<<(V * (HC / 4) + 255) / 256, 256>>>(out, V * (HC / 4));
}

// round 4
// speedup vs baseline: 2.1708x; 1.7707x over previous
#include <cuda_runtime.h>
#include <cuda_bf16.h>

// Problem constants (GATLayer): V=100000, E=1600000, Fin=128, H=4, Cout=32
#define FIN   128
#define HC    128   // H*Cout
#define NHEAD 4
#define MAXV  100000
#define MAXE  1600000
#define SCAN_BLK 1024

// -------- scratch (static device globals; allocation-free rule) --------
__device__ __align__(16) float g_z[MAXV * HC];        // 51.2 MB
__device__ __align__(16) float g_ssrc[MAXV * NHEAD];
__device__ __align__(16) float g_sdst[MAXV * NHEAD];
__device__ int g_deg[MAXV];
__device__ int g_off[MAXV + 1];
__device__ int g_cur[MAXV];
__device__ int g_bsum[256];
__device__ int g_srcs[MAXE];
__device__ int g_is32;

// -------- helpers --------
__device__ __forceinline__ float lrelu(float v) {
    return v >= 0.f ? v : 0.2f * v;
}

// packed fp32x2 FMA (Blackwell): d = a*b + d, componentwise on 2 packed floats
__device__ __forceinline__ void ffma2(unsigned long long& d,
                                      unsigned long long a,
                                      unsigned long long b) {
    asm("fma.rn.f32x2 %0, %1, %2, %0;" : "+l"(d) : "l"(a), "l"(b));
}
__device__ __forceinline__ unsigned long long pack2(float x) {
    unsigned long long r;
    asm("mov.b64 %0, {%1, %1};" : "=l"(r) : "f"(x));
    return r;
}
__device__ __forceinline__ void unpack2(unsigned long long p, float& lo, float& hi) {
    asm("mov.b64 {%0, %1}, %2;" : "=f"(lo), "=f"(hi) : "l"(p));
}

// ======================================================================
// dtype probe: int64 edge_index has all odd 32-bit words == 0
// ======================================================================
__global__ void flag_reset_kernel() {
    if (threadIdx.x == 0) g_is32 = 0;
}
__global__ void detect_kernel(const unsigned int* __restrict__ w, int n_words) {
    int i = blockIdx.x * blockDim.x + threadIdx.x;
    int j = 2 * i + 1;
    if (j < n_words && w[j] != 0u) g_is32 = 1;
}

// ======================================================================
// CSR build
// ======================================================================
__global__ void zero_deg_kernel(int V) {
    int v = blockIdx.x * blockDim.x + threadIdx.x;
    if (v < V) g_deg[v] = 0;
}

__global__ void hist_kernel(const void* __restrict__ ei, int E) {
    int e = blockIdx.x * blockDim.x + threadIdx.x;
    if (e >= E) return;
    int dst;
    if (g_is32) dst = ((const int*)ei)[E + e];
    else        dst = (int)((const long long*)ei)[(long long)E + e];
    atomicAdd(&g_deg[dst], 1);
}

// P1: per-block reduce of deg -> g_bsum[b]
__global__ void scan_reduce_kernel(int V) {
    __shared__ int sh[SCAN_BLK];
    int t = threadIdx.x;
    int v = blockIdx.x * SCAN_BLK + t;
    sh[t] = (v < V) ? g_deg[v] : 0;
    __syncthreads();
#pragma unroll
    for (int s = SCAN_BLK / 2; s > 0; s >>= 1) {
        if (t < s) sh[t] += sh[t + s];
        __syncthreads();
    }
    if (t == 0) g_bsum[blockIdx.x] = sh[0];
}

// P2: exclusive scan of nb block sums (nb <= 128), one block of 128
__global__ void scan_sums_kernel(int nb) {
    __shared__ int sh[128];
    int t = threadIdx.x;
    int x = (t < nb) ? g_bsum[t] : 0;
    sh[t] = x;
    __syncthreads();
#pragma unroll
    for (int off = 1; off < 128; off <<= 1) {
        int v = (t >= off) ? sh[t - off] : 0;
        __syncthreads();
        sh[t] += v;
        __syncthreads();
    }
    if (t < nb) g_bsum[t] = sh[t] - x;   // exclusive
}

// P3: per-block exclusive scan of deg + block offset -> g_off, g_cur
__global__ void scan_final_kernel(int V) {
    __shared__ int sh[SCAN_BLK];
    int t = threadIdx.x;
    int v = blockIdx.x * SCAN_BLK + t;
    int x = (v < V) ? g_deg[v] : 0;
    sh[t] = x;
    __syncthreads();
#pragma unroll
    for (int off = 1; off < SCAN_BLK; off <<= 1) {
        int u = (t >= off) ? sh[t - off] : 0;
        __syncthreads();
        sh[t] += u;
        __syncthreads();
    }
    int excl = sh[t] - x + g_bsum[blockIdx.x];
    if (v < V) {
        g_off[v] = excl;
        g_cur[v] = excl;
        if (v == V - 1) g_off[V] = excl + x;
    }
}

__global__ void scatter_kernel(const void* __restrict__ ei, int E) {
    int e = blockIdx.x * blockDim.x + threadIdx.x;
    if (e >= E) return;
    int src, dst;
    if (g_is32) {
        const int* p = (const int*)ei;
        src = p[e]; dst = p[E + e];
    } else {
        const long long* p = (const long long*)ei;
        src = (int)p[e]; dst = (int)p[(long long)E + e];
    }
    int pos = atomicAdd(&g_cur[dst], 1);
    g_srcs[pos] = src;
}

// ======================================================================
// GEMM: z = x @ W via packed fp32x2 FMA.
// BM=128, BN=128(full), BK=16, 256 threads, 8x8 micro-tile with
// row-paired accumulators (x row-pairs packed for free from LDS.128).
// Fused epilogue: per-vertex attention scores via 4-lane shfl reduce.
// ======================================================================
#define BM 128
#define BK 16
typedef unsigned long long u64;

__global__ void __launch_bounds__(256, 2)
gemm_kernel(const float* __restrict__ x,
            const float* __restrict__ W,
            const float* __restrict__ a_src,
            const float* __restrict__ a_dst, int V) {
    __shared__ float Ws[BK][HC];         // 8 KB
    __shared__ float xsT[BK][BM + 4];    // transposed x tile, 8.25 KB

    int tid = threadIdx.x;
    int tx = tid & 15;      // col group: cols [tx*8, tx*8+8)
    int ty = tid >> 4;      // row group: rows [ty*8, ty*8+8)
    int row0 = blockIdx.x * BM;

    u64 acc[4][8];          // [row-pair][col], each = {row 2rp, row 2rp+1}
#pragma unroll
    for (int i = 0; i < 4; i++)
#pragma unroll
        for (int j = 0; j < 8; j++) acc[i][j] = 0ull;

    for (int kb = 0; kb < FIN; kb += BK) {
        // Ws: 16x128 floats = 512 float4, 2 per thread (coalesced)
#pragma unroll
        for (int i = 0; i < 2; i++) {
            int f = i * 256 + tid;
            int wr = f >> 5, wc4 = f & 31;
            *(float4*)&Ws[wr][wc4 * 4] =
                *(const float4*)&W[(kb + wr) * HC + wc4 * 4];
        }
        // xsT: transpose 128-rows x 16-k tile. 512 float4 loads, scatter STS.
#pragma unroll
        for (int i = 0; i < 2; i++) {
            int f = i * 256 + tid;
            int r = f >> 2, c4 = f & 3;
            float4 v = make_float4(0.f, 0.f, 0.f, 0.f);
            if (row0 + r < V)
                v = *(const float4*)&x[(size_t)(row0 + r) * FIN + kb + c4 * 4];
            xsT[c4 * 4 + 0][r] = v.x;
            xsT[c4 * 4 + 1][r] = v.y;
            xsT[c4 * 4 + 2][r] = v.z;
            xsT[c4 * 4 + 3][r] = v.w;
        }
        __syncthreads();

#pragma unroll
        for (int k = 0; k < BK; k++) {
            // 4 packed row-pairs directly from shared (rows ty*8 .. ty*8+7)
            ulonglong2 xa = *(const ulonglong2*)&xsT[k][ty * 8];
            ulonglong2 xb = *(const ulonglong2*)&xsT[k][ty * 8 + 4];
            u64 xp[4] = {xa.x, xa.y, xb.x, xb.y};
            float4 w0 = *(const float4*)&Ws[k][tx * 8];
            float4 w1 = *(const float4*)&Ws[k][tx * 8 + 4];
            u64 wd[8] = {pack2(w0.x), pack2(w0.y), pack2(w0.z), pack2(w0.w),
                         pack2(w1.x), pack2(w1.y), pack2(w1.z), pack2(w1.w)};
#pragma unroll
            for (int i = 0; i < 4; i++)
#pragma unroll
                for (int j = 0; j < 8; j++)
                    ffma2(acc[i][j], xp[i], wd[j]);
        }
        __syncthreads();
    }

    // epilogue: attention vectors for my 8 channels (head h = tx>>2)
    float as[8], ad[8];
#pragma unroll
    for (int j = 0; j < 8; j++) {
        as[j] = __ldg(&a_src[tx * 8 + j]);
        ad[j] = __ldg(&a_dst[tx * 8 + j]);
    }

#pragma unroll
    for (int rp = 0; rp < 4; rp++) {
        float lo[8], hi[8];
#pragma unroll
        for (int j = 0; j < 8; j++) unpack2(acc[rp][j], lo[j], hi[j]);

#pragma unroll
        for (int half = 0; half < 2; half++) {
            float* rowv = half ? hi : lo;
            int r = row0 + ty * 8 + rp * 2 + half;
            float ps = 0.f, pd = 0.f;
#pragma unroll
            for (int j = 0; j < 8; j++) {
                ps += rowv[j] * as[j];
                pd += rowv[j] * ad[j];
            }
            ps += __shfl_xor_sync(0xffffffffu, ps, 1);
            pd += __shfl_xor_sync(0xffffffffu, pd, 1);
            ps += __shfl_xor_sync(0xffffffffu, ps, 2);
            pd += __shfl_xor_sync(0xffffffffu, pd, 2);

            if (r < V) {
                *(float4*)&g_z[(size_t)r * HC + tx * 8] =
                    make_float4(rowv[0], rowv[1], rowv[2], rowv[3]);
                *(float4*)&g_z[(size_t)r * HC + tx * 8 + 4] =
                    make_float4(rowv[4], rowv[5], rowv[6], rowv[7]);
                if ((tx & 3) == 0) {
                    int h = tx >> 2;
                    g_ssrc[r * 4 + h] = ps;
                    g_sdst[r * 4 + h] = pd;
                }
            }
        }
    }
}

// ======================================================================
// Aggregation: one warp per dst vertex. Walk CSR segment, accumulate
// weighted z and denom in registers, fused divide + ELU, single write.
//   alpha = exp(e)/sum exp(e)  (max-shift algebraically cancels; e=O(5))
// ======================================================================
__global__ void agg_kernel(float* __restrict__ out, int V) {
    int d = (blockIdx.x * blockDim.x + threadIdx.x) >> 5;
    int lane = threadIdx.x & 31;
    if (d >= V) return;

    int beg = g_off[d], end = g_off[d + 1];
    int h = lane >> 3;
    float sd = g_sdst[d * 4 + h];

    float4 acc = make_float4(0.f, 0.f, 0.f, 0.f);
    float den = 0.f;

    for (int base = beg; base < end; base += 32) {
        int idx = base + lane;
        int my_s = (idx < end) ? g_srcs[idx] : 0;
        int n = min(32, end - base);
#pragma unroll 4
        for (int t = 0; t < n; t++) {
            int s = __shfl_sync(0xffffffffu, my_s, t);
            float w = __expf(lrelu(g_ssrc[s * 4 + h] + sd));
            den += w;
            float4 zv = *(const float4*)&g_z[(size_t)s * HC + lane * 4];
            acc.x += w * zv.x; acc.y += w * zv.y;
            acc.z += w * zv.z; acc.w += w * zv.w;
        }
    }

    float inv = 1.f / (den + 1e-9f);
    acc.x *= inv; acc.y *= inv; acc.z *= inv; acc.w *= inv;
    acc.x = acc.x > 0.f ? acc.x : expm1f(acc.x);
    acc.y = acc.y > 0.f ? acc.y : expm1f(acc.y);
    acc.z = acc.z > 0.f ? acc.z : expm1f(acc.z);
    acc.w = acc.w > 0.f ? acc.w : expm1f(acc.w);
    *(float4*)&out[(size_t)d * HC + lane * 4] = acc;
}

// ======================================================================
extern "C" void kernel_launch(void* const* d_in, const int* in_sizes, int n_in,
                              void* d_out, int out_size) {
    const float* x     = (const float*)d_in[0];
    const void*  ei    = d_in[1];
    const float* W     = (const float*)d_in[2];
    const float* a_src = (const float*)d_in[3];
    const float* a_dst = (const float*)d_in[4];
    float* out = (float*)d_out;

    int V = in_sizes[0] / FIN;
    int E = in_sizes[1] / 2;
    int nb = (V + SCAN_BLK - 1) / SCAN_BLK;   // <= 128 for V <= 131072

    // dtype probe (int32 vs int64 edge_index)
    flag_reset_kernel<<<1, 32>>>();
    int scan_words = 2 * E;
    if (scan_words > 262144) scan_words = 262144;
    detect_kernel<<<(scan_words / 2 + 255) / 256, 256>>>(
        (const unsigned int*)ei, scan_words);

    // CSR build
    zero_deg_kernel<<<(V + 1023) / 1024, 1024>>>(V);
    hist_kernel<<<(E + 255) / 256, 256>>>(ei, E);
    scan_reduce_kernel<<<nb, SCAN_BLK>>>(V);
    scan_sums_kernel<<<1, 128>>>(nb);
    scan_final_kernel<<<nb, SCAN_BLK>>>(V);
    scatter_kernel<<<(E + 255) / 256, 256>>>(ei, E);

    // GEMM + scores
    gemm_kernel<<<(V + BM - 1) / BM, 256>>>(x, W, a_src, a_dst, V);

    // aggregation (warp per dst) with fused softmax-normalize + ELU
    agg_kernel<<<(V + 7) / 8, 256>>>(out, V);
}

// round 5
// speedup vs baseline: 2.3834x; 1.0979x over previous
#include <cuda_runtime.h>
#include <cuda_bf16.h>

// Problem constants (GATLayer): V=100000, E=1600000, Fin=128, H=4, Cout=32
#define FIN   128
#define HC    128   // H*Cout
#define NHEAD 4
#define MAXV  100000
#define MAXE  1600000
#define SCAN_BLK 1024

// -------- scratch (static device globals; allocation-free rule) --------
__device__ __align__(16) float g_z[MAXV * HC];        // 51.2 MB
__device__ __align__(16) float g_ssrc[MAXV * NHEAD];
__device__ __align__(16) float g_sdst[MAXV * NHEAD];
__device__ int g_deg[MAXV];
__device__ int g_off[MAXV + 1];
__device__ int g_cur[MAXV];
__device__ int g_bsum[256];
__device__ int g_srcs[MAXE];
__device__ int g_is32;

// -------- helpers --------
__device__ __forceinline__ float lrelu(float v) {
    return v >= 0.f ? v : 0.2f * v;
}

// packed fp32x2 FMA (Blackwell): d = a*b + d, componentwise
__device__ __forceinline__ void ffma2(unsigned long long& d,
                                      unsigned long long a,
                                      unsigned long long b) {
    asm("fma.rn.f32x2 %0, %1, %2, %0;" : "+l"(d) : "l"(a), "l"(b));
}
__device__ __forceinline__ unsigned long long pack2(float x) {
    unsigned long long r;
    asm("mov.b64 %0, {%1, %1};" : "=l"(r) : "f"(x));
    return r;
}
__device__ __forceinline__ void unpack2(unsigned long long p, float& lo, float& hi) {
    asm("mov.b64 {%0, %1}, %2;" : "=f"(lo), "=f"(hi) : "l"(p));
}

// ======================================================================
// probe + deg-zero (fused): int64 edge_index has all odd 32-bit words 0
// ======================================================================
__global__ void flag_reset_kernel() {
    if (threadIdx.x == 0) g_is32 = 0;
}

__global__ void detect_zero_kernel(const unsigned int* __restrict__ w,
                                   int n_words, int V) {
    int i = blockIdx.x * blockDim.x + threadIdx.x;
    int j = 2 * i + 1;
    if (j < n_words && w[j] != 0u) g_is32 = 1;
    if (i < V) g_deg[i] = 0;
}

// ======================================================================
// CSR build
// ======================================================================
__global__ void hist_kernel(const void* __restrict__ ei, int E) {
    int e = blockIdx.x * blockDim.x + threadIdx.x;
    if (e >= E) return;
    int dst;
    if (g_is32) dst = ((const int*)ei)[E + e];
    else        dst = (int)((const long long*)ei)[(long long)E + e];
    atomicAdd(&g_deg[dst], 1);
}

__global__ void scan_reduce_kernel(int V) {
    __shared__ int sh[SCAN_BLK];
    int t = threadIdx.x;
    int v = blockIdx.x * SCAN_BLK + t;
    sh[t] = (v < V) ? g_deg[v] : 0;
    __syncthreads();
#pragma unroll
    for (int s = SCAN_BLK / 2; s > 0; s >>= 1) {
        if (t < s) sh[t] += sh[t + s];
        __syncthreads();
    }
    if (t == 0) g_bsum[blockIdx.x] = sh[0];
}

__global__ void scan_sums_kernel(int nb) {
    __shared__ int sh[128];
    int t = threadIdx.x;
    int x = (t < nb) ? g_bsum[t] : 0;
    sh[t] = x;
    __syncthreads();
#pragma unroll
    for (int off = 1; off < 128; off <<= 1) {
        int v = (t >= off) ? sh[t - off] : 0;
        __syncthreads();
        sh[t] += v;
        __syncthreads();
    }
    if (t < nb) g_bsum[t] = sh[t] - x;   // exclusive
}

__global__ void scan_final_kernel(int V) {
    __shared__ int sh[SCAN_BLK];
    int t = threadIdx.x;
    int v = blockIdx.x * SCAN_BLK + t;
    int x = (v < V) ? g_deg[v] : 0;
    sh[t] = x;
    __syncthreads();
#pragma unroll
    for (int off = 1; off < SCAN_BLK; off <<= 1) {
        int u = (t >= off) ? sh[t - off] : 0;
        __syncthreads();
        sh[t] += u;
        __syncthreads();
    }
    int excl = sh[t] - x + g_bsum[blockIdx.x];
    if (v < V) {
        g_off[v] = excl;
        g_cur[v] = excl;
        if (v == V - 1) g_off[V] = excl + x;
    }
}

__global__ void scatter_kernel(const void* __restrict__ ei, int E) {
    int e = blockIdx.x * blockDim.x + threadIdx.x;
    if (e >= E) return;
    int src, dst;
    if (g_is32) {
        const int* p = (const int*)ei;
        src = p[e]; dst = p[E + e];
    } else {
        const long long* p = (const long long*)ei;
        src = (int)p[e]; dst = (int)p[(long long)E + e];
    }
    int pos = atomicAdd(&g_cur[dst], 1);
    g_srcs[pos] = src;
}

// ======================================================================
// GEMM: z = x @ W via packed fp32x2 FMA.
// BM=128, BN=128(full), BK=16, 256 threads, 8x8 micro-tile with
// row-paired accumulators. Fused epilogue: per-vertex attention scores.
// ======================================================================
#define BM 128
#define BK 16
typedef unsigned long long u64;

__global__ void __launch_bounds__(256, 2)
gemm_kernel(const float* __restrict__ x,
            const float* __restrict__ W,
            const float* __restrict__ a_src,
            const float* __restrict__ a_dst, int V) {
    __shared__ float Ws[BK][HC];
    __shared__ float xsT[BK][BM + 4];

    int tid = threadIdx.x;
    int tx = tid & 15;
    int ty = tid >> 4;
    int row0 = blockIdx.x * BM;

    u64 acc[4][8];
#pragma unroll
    for (int i = 0; i < 4; i++)
#pragma unroll
        for (int j = 0; j < 8; j++) acc[i][j] = 0ull;

    for (int kb = 0; kb < FIN; kb += BK) {
#pragma unroll
        for (int i = 0; i < 2; i++) {
            int f = i * 256 + tid;
            int wr = f >> 5, wc4 = f & 31;
            *(float4*)&Ws[wr][wc4 * 4] =
                *(const float4*)&W[(kb + wr) * HC + wc4 * 4];
        }
#pragma unroll
        for (int i = 0; i < 2; i++) {
            int f = i * 256 + tid;
            int r = f >> 2, c4 = f & 3;
            float4 v = make_float4(0.f, 0.f, 0.f, 0.f);
            if (row0 + r < V)
                v = *(const float4*)&x[(size_t)(row0 + r) * FIN + kb + c4 * 4];
            xsT[c4 * 4 + 0][r] = v.x;
            xsT[c4 * 4 + 1][r] = v.y;
            xsT[c4 * 4 + 2][r] = v.z;
            xsT[c4 * 4 + 3][r] = v.w;
        }
        __syncthreads();

#pragma unroll
        for (int k = 0; k < BK; k++) {
            ulonglong2 xa = *(const ulonglong2*)&xsT[k][ty * 8];
            ulonglong2 xb = *(const ulonglong2*)&xsT[k][ty * 8 + 4];
            u64 xp[4] = {xa.x, xa.y, xb.x, xb.y};
            float4 w0 = *(const float4*)&Ws[k][tx * 8];
            float4 w1 = *(const float4*)&Ws[k][tx * 8 + 4];
            u64 wd[8] = {pack2(w0.x), pack2(w0.y), pack2(w0.z), pack2(w0.w),
                         pack2(w1.x), pack2(w1.y), pack2(w1.z), pack2(w1.w)};
#pragma unroll
            for (int i = 0; i < 4; i++)
#pragma unroll
                for (int j = 0; j < 8; j++)
                    ffma2(acc[i][j], xp[i], wd[j]);
        }
        __syncthreads();
    }

    float as[8], ad[8];
#pragma unroll
    for (int j = 0; j < 8; j++) {
        as[j] = __ldg(&a_src[tx * 8 + j]);
        ad[j] = __ldg(&a_dst[tx * 8 + j]);
    }

#pragma unroll
    for (int rp = 0; rp < 4; rp++) {
        float lo[8], hi[8];
#pragma unroll
        for (int j = 0; j < 8; j++) unpack2(acc[rp][j], lo[j], hi[j]);

#pragma unroll
        for (int half = 0; half < 2; half++) {
            float* rowv = half ? hi : lo;
            int r = row0 + ty * 8 + rp * 2 + half;
            float ps = 0.f, pd = 0.f;
#pragma unroll
            for (int j = 0; j < 8; j++) {
                ps += rowv[j] * as[j];
                pd += rowv[j] * ad[j];
            }
            ps += __shfl_xor_sync(0xffffffffu, ps, 1);
            pd += __shfl_xor_sync(0xffffffffu, pd, 1);
            ps += __shfl_xor_sync(0xffffffffu, ps, 2);
            pd += __shfl_xor_sync(0xffffffffu, pd, 2);

            if (r < V) {
                *(float4*)&g_z[(size_t)r * HC + tx * 8] =
                    make_float4(rowv[0], rowv[1], rowv[2], rowv[3]);
                *(float4*)&g_z[(size_t)r * HC + tx * 8 + 4] =
                    make_float4(rowv[4], rowv[5], rowv[6], rowv[7]);
                if ((tx & 3) == 0) {
                    int h = tx >> 2;
                    g_ssrc[r * 4 + h] = ps;
                    g_sdst[r * 4 + h] = pd;
                }
            }
        }
    }
}

// ======================================================================
// Aggregation: one warp per dst vertex, CSR walk, registers-only
// softmax (max-shift algebraically cancels), fused divide + ELU.
// ======================================================================
__global__ void agg_kernel(float* __restrict__ out, int V) {
    int d = (blockIdx.x * blockDim.x + threadIdx.x) >> 5;
    int lane = threadIdx.x & 31;
    if (d >= V) return;

    int beg = g_off[d], end = g_off[d + 1];
    int h = lane >> 3;
    float sd = g_sdst[d * 4 + h];

    float4 acc = make_float4(0.f, 0.f, 0.f, 0.f);
    float den = 0.f;

    for (int base = beg; base < end; base += 32) {
        int idx = base + lane;
        int my_s = (idx < end) ? g_srcs[idx] : 0;
        int n = min(32, end - base);
#pragma unroll 4
        for (int t = 0; t < n; t++) {
            int s = __shfl_sync(0xffffffffu, my_s, t);
            float w = __expf(lrelu(g_ssrc[s * 4 + h] + sd));
            den += w;
            float4 zv = *(const float4*)&g_z[(size_t)s * HC + lane * 4];
            acc.x += w * zv.x; acc.y += w * zv.y;
            acc.z += w * zv.z; acc.w += w * zv.w;
        }
    }

    float inv = 1.f / (den + 1e-9f);
    acc.x *= inv; acc.y *= inv; acc.z *= inv; acc.w *= inv;
    acc.x = acc.x > 0.f ? acc.x : expm1f(acc.x);
    acc.y = acc.y > 0.f ? acc.y : expm1f(acc.y);
    acc.z = acc.z > 0.f ? acc.z : expm1f(acc.z);
    acc.w = acc.w > 0.f ? acc.w : expm1f(acc.w);
    *(float4*)&out[(size_t)d * HC + lane * 4] = acc;
}

// ======================================================================
extern "C" void kernel_launch(void* const* d_in, const int* in_sizes, int n_in,
                              void* d_out, int out_size) {
    const float* x     = (const float*)d_in[0];
    const void*  ei    = d_in[1];
    const float* W     = (const float*)d_in[2];
    const float* a_src = (const float*)d_in[3];
    const float* a_dst = (const float*)d_in[4];
    float* out = (float*)d_out;

    int V = in_sizes[0] / FIN;
    int E = in_sizes[1] / 2;
    int nb = (V + SCAN_BLK - 1) / SCAN_BLK;

    // Side stream + fork/join events (created per call; kernel_launch only
    // runs a few times — eager + capture — so not destroying them is fine
    // and avoids destroy-during-capture hazards). No device memory involved.
    cudaStream_t s1;
    cudaStreamCreateWithFlags(&s1, cudaStreamNonBlocking);
    cudaEvent_t ev_fork, ev_join;
    cudaEventCreateWithFlags(&ev_fork, cudaEventDisableTiming);
    cudaEventCreateWithFlags(&ev_join, cudaEventDisableTiming);

    // fork: side stream handles the entire edge/CSR pipeline
    cudaEventRecord(ev_fork, 0);
    cudaStreamWaitEvent(s1, ev_fork, 0);

    int scan_words = 2 * E;
    if (scan_words > 262144) scan_words = 262144;
    int dz_threads = (V > scan_words / 2) ? V : scan_words / 2;

    flag_reset_kernel<<<1, 32, 0, s1>>>();
    detect_zero_kernel<<<(dz_threads + 255) / 256, 256, 0, s1>>>(
        (const unsigned int*)ei, scan_words, V);
    hist_kernel<<<(E + 255) / 256, 256, 0, s1>>>(ei, E);
    scan_reduce_kernel<<<nb, SCAN_BLK, 0, s1>>>(V);
    scan_sums_kernel<<<1, 128, 0, s1>>>(nb);
    scan_final_kernel<<<nb, SCAN_BLK, 0, s1>>>(V);
    scatter_kernel<<<(E + 255) / 256, 256, 0, s1>>>(ei, E);

    // main stream: GEMM + attention scores (independent of edges)
    gemm_kernel<<<(V + BM - 1) / BM, 256>>>(x, W, a_src, a_dst, V);

    // join: agg needs both CSR and z/scores
    cudaEventRecord(ev_join, s1);
    cudaStreamWaitEvent(0, ev_join, 0);

    agg_kernel<<<(V + 7) / 8, 256>>>(out, V);
}

// round 6
// speedup vs baseline: 2.6716x; 1.1209x over previous
#include <cuda_runtime.h>
#include <cuda_bf16.h>
#include <cuda_fp16.h>

// Problem constants (GATLayer): V=100000, E=1600000, Fin=128, H=4, Cout=32
#define FIN   128
#define HC    128   // H*Cout
#define NHEAD 4
#define MAXV  100000
#define MAXE  1600000
#define SCAN_BLK 1024

// -------- scratch (static device globals; allocation-free rule) --------
__device__ __align__(16) __half g_z[MAXV * HC];       // 25.6 MB (fp16 z)
__device__ __align__(16) float g_ssrc[MAXV * NHEAD];
__device__ __align__(16) float g_sdst[MAXV * NHEAD];
__device__ int g_deg[MAXV];
__device__ int g_off[MAXV + 1];
__device__ int g_cur[MAXV];
__device__ int g_bsum[256];
__device__ int g_srcs[MAXE];
__device__ int g_is32;

// -------- helpers --------
__device__ __forceinline__ float lrelu(float v) {
    return v >= 0.f ? v : 0.2f * v;
}

// packed fp32x2 FMA (Blackwell): d = a*b + d, componentwise
__device__ __forceinline__ void ffma2(unsigned long long& d,
                                      unsigned long long a,
                                      unsigned long long b) {
    asm("fma.rn.f32x2 %0, %1, %2, %0;" : "+l"(d) : "l"(a), "l"(b));
}
__device__ __forceinline__ unsigned long long pack2(float x) {
    unsigned long long r;
    asm("mov.b64 %0, {%1, %1};" : "=l"(r) : "f"(x));
    return r;
}
__device__ __forceinline__ void unpack2(unsigned long long p, float& lo, float& hi) {
    asm("mov.b64 {%0, %1}, %2;" : "=f"(lo), "=f"(hi) : "l"(p));
}

// ======================================================================
// probe + deg-zero (fused): int64 edge_index has all odd 32-bit words 0
// ======================================================================
__global__ void flag_reset_kernel() {
    if (threadIdx.x == 0) g_is32 = 0;
}

__global__ void detect_zero_kernel(const unsigned int* __restrict__ w,
                                   int n_words, int V) {
    int i = blockIdx.x * blockDim.x + threadIdx.x;
    int j = 2 * i + 1;
    if (j < n_words && w[j] != 0u) g_is32 = 1;
    if (i < V) g_deg[i] = 0;
}

// ======================================================================
// CSR build
// ======================================================================
__global__ void hist_kernel(const void* __restrict__ ei, int E) {
    int e = blockIdx.x * blockDim.x + threadIdx.x;
    if (e >= E) return;
    int dst;
    if (g_is32) dst = ((const int*)ei)[E + e];
    else        dst = (int)((const long long*)ei)[(long long)E + e];
    atomicAdd(&g_deg[dst], 1);
}

__global__ void scan_reduce_kernel(int V) {
    __shared__ int sh[SCAN_BLK];
    int t = threadIdx.x;
    int v = blockIdx.x * SCAN_BLK + t;
    sh[t] = (v < V) ? g_deg[v] : 0;
    __syncthreads();
#pragma unroll
    for (int s = SCAN_BLK / 2; s > 0; s >>= 1) {
        if (t < s) sh[t] += sh[t + s];
        __syncthreads();
    }
    if (t == 0) g_bsum[blockIdx.x] = sh[0];
}

__global__ void scan_sums_kernel(int nb) {
    __shared__ int sh[128];
    int t = threadIdx.x;
    int x = (t < nb) ? g_bsum[t] : 0;
    sh[t] = x;
    __syncthreads();
#pragma unroll
    for (int off = 1; off < 128; off <<= 1) {
        int v = (t >= off) ? sh[t - off] : 0;
        __syncthreads();
        sh[t] += v;
        __syncthreads();
    }
    if (t < nb) g_bsum[t] = sh[t] - x;   // exclusive
}

__global__ void scan_final_kernel(int V) {
    __shared__ int sh[SCAN_BLK];
    int t = threadIdx.x;
    int v = blockIdx.x * SCAN_BLK + t;
    int x = (v < V) ? g_deg[v] : 0;
    sh[t] = x;
    __syncthreads();
#pragma unroll
    for (int off = 1; off < SCAN_BLK; off <<= 1) {
        int u = (t >= off) ? sh[t - off] : 0;
        __syncthreads();
        sh[t] += u;
        __syncthreads();
    }
    int excl = sh[t] - x + g_bsum[blockIdx.x];
    if (v < V) {
        g_off[v] = excl;
        g_cur[v] = excl;
        if (v == V - 1) g_off[V] = excl + x;
    }
}

__global__ void scatter_kernel(const void* __restrict__ ei, int E) {
    int e = blockIdx.x * blockDim.x + threadIdx.x;
    if (e >= E) return;
    int src, dst;
    if (g_is32) {
        const int* p = (const int*)ei;
        src = p[e]; dst = p[E + e];
    } else {
        const long long* p = (const long long*)ei;
        src = (int)p[e]; dst = (int)p[(long long)E + e];
    }
    int pos = atomicAdd(&g_cur[dst], 1);
    g_srcs[pos] = src;
}

// ======================================================================
// GEMM: z = x @ W via packed fp32x2 FMA.
// BM=128, BN=128(full), BK=16, 256 threads, 8x8 micro-tile with
// row-paired accumulators. Fused epilogue: per-vertex attention scores
// (fp32, from registers) + z stored as fp16.
// ======================================================================
#define BM 128
#define BK 16
typedef unsigned long long u64;

__global__ void __launch_bounds__(256, 2)
gemm_kernel(const float* __restrict__ x,
            const float* __restrict__ W,
            const float* __restrict__ a_src,
            const float* __restrict__ a_dst, int V) {
    __shared__ float Ws[BK][HC];
    __shared__ float xsT[BK][BM + 4];

    int tid = threadIdx.x;
    int tx = tid & 15;
    int ty = tid >> 4;
    int row0 = blockIdx.x * BM;

    u64 acc[4][8];
#pragma unroll
    for (int i = 0; i < 4; i++)
#pragma unroll
        for (int j = 0; j < 8; j++) acc[i][j] = 0ull;

    for (int kb = 0; kb < FIN; kb += BK) {
#pragma unroll
        for (int i = 0; i < 2; i++) {
            int f = i * 256 + tid;
            int wr = f >> 5, wc4 = f & 31;
            *(float4*)&Ws[wr][wc4 * 4] =
                *(const float4*)&W[(kb + wr) * HC + wc4 * 4];
        }
#pragma unroll
        for (int i = 0; i < 2; i++) {
            int f = i * 256 + tid;
            int r = f >> 2, c4 = f & 3;
            float4 v = make_float4(0.f, 0.f, 0.f, 0.f);
            if (row0 + r < V)
                v = *(const float4*)&x[(size_t)(row0 + r) * FIN + kb + c4 * 4];
            xsT[c4 * 4 + 0][r] = v.x;
            xsT[c4 * 4 + 1][r] = v.y;
            xsT[c4 * 4 + 2][r] = v.z;
            xsT[c4 * 4 + 3][r] = v.w;
        }
        __syncthreads();

#pragma unroll
        for (int k = 0; k < BK; k++) {
            ulonglong2 xa = *(const ulonglong2*)&xsT[k][ty * 8];
            ulonglong2 xb = *(const ulonglong2*)&xsT[k][ty * 8 + 4];
            u64 xp[4] = {xa.x, xa.y, xb.x, xb.y};
            float4 w0 = *(const float4*)&Ws[k][tx * 8];
            float4 w1 = *(const float4*)&Ws[k][tx * 8 + 4];
            u64 wd[8] = {pack2(w0.x), pack2(w0.y), pack2(w0.z), pack2(w0.w),
                         pack2(w1.x), pack2(w1.y), pack2(w1.z), pack2(w1.w)};
#pragma unroll
            for (int i = 0; i < 4; i++)
#pragma unroll
                for (int j = 0; j < 8; j++)
                    ffma2(acc[i][j], xp[i], wd[j]);
        }
        __syncthreads();
    }

    float as[8], ad[8];
#pragma unroll
    for (int j = 0; j < 8; j++) {
        as[j] = __ldg(&a_src[tx * 8 + j]);
        ad[j] = __ldg(&a_dst[tx * 8 + j]);
    }

#pragma unroll
    for (int rp = 0; rp < 4; rp++) {
        float lo[8], hi[8];
#pragma unroll
        for (int j = 0; j < 8; j++) unpack2(acc[rp][j], lo[j], hi[j]);

#pragma unroll
        for (int half = 0; half < 2; half++) {
            float* rowv = half ? hi : lo;
            int r = row0 + ty * 8 + rp * 2 + half;
            float ps = 0.f, pd = 0.f;
#pragma unroll
            for (int j = 0; j < 8; j++) {
                ps += rowv[j] * as[j];
                pd += rowv[j] * ad[j];
            }
            ps += __shfl_xor_sync(0xffffffffu, ps, 1);
            pd += __shfl_xor_sync(0xffffffffu, pd, 1);
            ps += __shfl_xor_sync(0xffffffffu, ps, 2);
            pd += __shfl_xor_sync(0xffffffffu, pd, 2);

            if (r < V) {
                // store z as fp16: 8 channels -> 4 half2 = 16 bytes
                __half2 hp[4];
                hp[0] = __floats2half2_rn(rowv[0], rowv[1]);
                hp[1] = __floats2half2_rn(rowv[2], rowv[3]);
                hp[2] = __floats2half2_rn(rowv[4], rowv[5]);
                hp[3] = __floats2half2_rn(rowv[6], rowv[7]);
                *(uint4*)&g_z[(size_t)r * HC + tx * 8] = *(uint4*)hp;
                if ((tx & 3) == 0) {
                    int h = tx >> 2;
                    g_ssrc[r * 4 + h] = ps;
                    g_sdst[r * 4 + h] = pd;
                }
            }
        }
    }
}

// ======================================================================
// Aggregation: one warp per dst vertex, CSR walk, fp16 z gather
// (256B/warp/edge), fp32 accumulate, fused softmax-normalize + ELU.
// ======================================================================
__global__ void agg_kernel(float* __restrict__ out, int V) {
    int d = (blockIdx.x * blockDim.x + threadIdx.x) >> 5;
    int lane = threadIdx.x & 31;
    if (d >= V) return;

    int beg = g_off[d], end = g_off[d + 1];
    int h = lane >> 3;
    float sd = g_sdst[d * 4 + h];

    float4 acc = make_float4(0.f, 0.f, 0.f, 0.f);
    float den = 0.f;

    for (int base = beg; base < end; base += 32) {
        int idx = base + lane;
        int my_s = (idx < end) ? g_srcs[idx] : 0;
        int n = min(32, end - base);
#pragma unroll 4
        for (int t = 0; t < n; t++) {
            int s = __shfl_sync(0xffffffffu, my_s, t);
            float w = __expf(lrelu(g_ssrc[s * 4 + h] + sd));
            den += w;
            uint2 raw = *(const uint2*)&g_z[(size_t)s * HC + lane * 4];
            float2 f0 = __half22float2(*(__half2*)&raw.x);
            float2 f1 = __half22float2(*(__half2*)&raw.y);
            acc.x += w * f0.x; acc.y += w * f0.y;
            acc.z += w * f1.x; acc.w += w * f1.y;
        }
    }

    float inv = 1.f / (den + 1e-9f);
    acc.x *= inv; acc.y *= inv; acc.z *= inv; acc.w *= inv;
    acc.x = acc.x > 0.f ? acc.x : expm1f(acc.x);
    acc.y = acc.y > 0.f ? acc.y : expm1f(acc.y);
    acc.z = acc.z > 0.f ? acc.z : expm1f(acc.z);
    acc.w = acc.w > 0.f ? acc.w : expm1f(acc.w);
    *(float4*)&out[(size_t)d * HC + lane * 4] = acc;
}

// ======================================================================
extern "C" void kernel_launch(void* const* d_in, const int* in_sizes, int n_in,
                              void* d_out, int out_size) {
    const float* x     = (const float*)d_in[0];
    const void*  ei    = d_in[1];
    const float* W     = (const float*)d_in[2];
    const float* a_src = (const float*)d_in[3];
    const float* a_dst = (const float*)d_in[4];
    float* out = (float*)d_out;

    int V = in_sizes[0] / FIN;
    int E = in_sizes[1] / 2;
    int nb = (V + SCAN_BLK - 1) / SCAN_BLK;

    // Side stream + fork/join events (created per call; kernel_launch only
    // runs a few times — eager + capture. No device memory involved.)
    cudaStream_t s1;
    cudaStreamCreateWithFlags(&s1, cudaStreamNonBlocking);
    cudaEvent_t ev_fork, ev_join;
    cudaEventCreateWithFlags(&ev_fork, cudaEventDisableTiming);
    cudaEventCreateWithFlags(&ev_join, cudaEventDisableTiming);

    // fork: side stream handles the entire edge/CSR pipeline
    cudaEventRecord(ev_fork, 0);
    cudaStreamWaitEvent(s1, ev_fork, 0);

    int scan_words = 2 * E;
    if (scan_words > 262144) scan_words = 262144;
    int dz_threads = (V > scan_words / 2) ? V : scan_words / 2;

    flag_reset_kernel<<<1, 32, 0, s1>>>();
    detect_zero_kernel<<<(dz_threads + 255) / 256, 256, 0, s1>>>(
        (const unsigned int*)ei, scan_words, V);
    hist_kernel<<<(E + 255) / 256, 256, 0, s1>>>(ei, E);
    scan_reduce_kernel<<<nb, SCAN_BLK, 0, s1>>>(V);
    scan_sums_kernel<<<1, 128, 0, s1>>>(nb);
    scan_final_kernel<<<nb, SCAN_BLK, 0, s1>>>(V);
    scatter_kernel<<<(E + 255) / 256, 256, 0, s1>>>(ei, E);

    // main stream: GEMM + attention scores (independent of edges)
    gemm_kernel<<<(V + BM - 1) / BM, 256>>>(x, W, a_src, a_dst, V);

    // join: agg needs both CSR and z/scores
    cudaEventRecord(ev_join, s1);
    cudaStreamWaitEvent(0, ev_join, 0);

    agg_kernel<<<(V + 7) / 8, 256>>>(out, V);
}

// round 7
// speedup vs baseline: 2.6863x; 1.0055x over previous
#include <cuda_runtime.h>
#include <cuda_bf16.h>
#include <cuda_fp16.h>

// Problem constants (GATLayer): V=100000, E=1600000, Fin=128, H=4, Cout=32
#define FIN   128
#define HC    128   // H*Cout
#define NHEAD 4
#define MAXV  100000
#define MAXE  1600000
#define SCAN_BLK 1024

// -------- scratch (static device globals; allocation-free rule) --------
__device__ __align__(16) __half g_z[MAXV * HC];       // 25.6 MB (fp16 z)
__device__ __align__(16) float g_ssrc[MAXV * NHEAD];
__device__ __align__(16) float g_sdst[MAXV * NHEAD];
__device__ int g_deg[MAXV];
__device__ int g_off[MAXV + 1];
__device__ int g_cur[MAXV];
__device__ int g_bsum[256];
__device__ int g_srcs[MAXE];
__device__ int g_is32;

// -------- helpers --------
__device__ __forceinline__ float lrelu(float v) {
    return fmaxf(v, 0.2f * v);   // branchless: equals LeakyReLU(0.2)
}

// packed fp32x2 FMA (Blackwell): d = a*b + d, componentwise
__device__ __forceinline__ void ffma2(unsigned long long& d,
                                      unsigned long long a,
                                      unsigned long long b) {
    asm("fma.rn.f32x2 %0, %1, %2, %0;" : "+l"(d) : "l"(a), "l"(b));
}
__device__ __forceinline__ unsigned long long pack2(float x) {
    unsigned long long r;
    asm("mov.b64 %0, {%1, %1};" : "=l"(r) : "f"(x));
    return r;
}
__device__ __forceinline__ unsigned long long pack2f(float lo, float hi) {
    unsigned long long r;
    asm("mov.b64 %0, {%1, %2};" : "=l"(r) : "f"(lo), "f"(hi));
    return r;
}
__device__ __forceinline__ void unpack2(unsigned long long p, float& lo, float& hi) {
    asm("mov.b64 {%0, %1}, %2;" : "=f"(lo), "=f"(hi) : "l"(p));
}

// ======================================================================
// probe + deg-zero (fused): int64 edge_index has all odd 32-bit words 0
// ======================================================================
__global__ void flag_reset_kernel() {
    if (threadIdx.x == 0) g_is32 = 0;
}

__global__ void detect_zero_kernel(const unsigned int* __restrict__ w,
                                   int n_words, int V) {
    int i = blockIdx.x * blockDim.x + threadIdx.x;
    int j = 2 * i + 1;
    if (j < n_words && w[j] != 0u) g_is32 = 1;
    if (i < V) g_deg[i] = 0;
}

// ======================================================================
// CSR build
// ======================================================================
__global__ void hist_kernel(const void* __restrict__ ei, int E) {
    int e = blockIdx.x * blockDim.x + threadIdx.x;
    if (e >= E) return;
    int dst;
    if (g_is32) dst = ((const int*)ei)[E + e];
    else        dst = (int)((const long long*)ei)[(long long)E + e];
    atomicAdd(&g_deg[dst], 1);
}

__global__ void scan_reduce_kernel(int V) {
    __shared__ int sh[SCAN_BLK];
    int t = threadIdx.x;
    int v = blockIdx.x * SCAN_BLK + t;
    sh[t] = (v < V) ? g_deg[v] : 0;
    __syncthreads();
#pragma unroll
    for (int s = SCAN_BLK / 2; s > 0; s >>= 1) {
        if (t < s) sh[t] += sh[t + s];
        __syncthreads();
    }
    if (t == 0) g_bsum[blockIdx.x] = sh[0];
}

__global__ void scan_sums_kernel(int nb) {
    __shared__ int sh[128];
    int t = threadIdx.x;
    int x = (t < nb) ? g_bsum[t] : 0;
    sh[t] = x;
    __syncthreads();
#pragma unroll
    for (int off = 1; off < 128; off <<= 1) {
        int v = (t >= off) ? sh[t - off] : 0;
        __syncthreads();
        sh[t] += v;
        __syncthreads();
    }
    if (t < nb) g_bsum[t] = sh[t] - x;   // exclusive
}

__global__ void scan_final_kernel(int V) {
    __shared__ int sh[SCAN_BLK];
    int t = threadIdx.x;
    int v = blockIdx.x * SCAN_BLK + t;
    int x = (v < V) ? g_deg[v] : 0;
    sh[t] = x;
    __syncthreads();
#pragma unroll
    for (int off = 1; off < SCAN_BLK; off <<= 1) {
        int u = (t >= off) ? sh[t - off] : 0;
        __syncthreads();
        sh[t] += u;
        __syncthreads();
    }
    int excl = sh[t] - x + g_bsum[blockIdx.x];
    if (v < V) {
        g_off[v] = excl;
        g_cur[v] = excl;
        if (v == V - 1) g_off[V] = excl + x;
    }
}

__global__ void scatter_kernel(const void* __restrict__ ei, int E) {
    int e = blockIdx.x * blockDim.x + threadIdx.x;
    if (e >= E) return;
    int src, dst;
    if (g_is32) {
        const int* p = (const int*)ei;
        src = p[e]; dst = p[E + e];
    } else {
        const long long* p = (const long long*)ei;
        src = (int)p[e]; dst = (int)p[(long long)E + e];
    }
    int pos = atomicAdd(&g_cur[dst], 1);
    g_srcs[pos] = src;
}

// ======================================================================
// GEMM: z = x @ W via packed fp32x2 FMA.
// BM=128, BN=128(full), BK=16, 256 threads, 8x8 micro-tile with
// row-paired accumulators. Fused epilogue: per-vertex attention scores
// (fp32, from registers) + z stored as fp16.
// ======================================================================
#define BM 128
#define BK 16
typedef unsigned long long u64;

__global__ void __launch_bounds__(256, 2)
gemm_kernel(const float* __restrict__ x,
            const float* __restrict__ W,
            const float* __restrict__ a_src,
            const float* __restrict__ a_dst, int V) {
    __shared__ float Ws[BK][HC];
    __shared__ float xsT[BK][BM + 4];

    int tid = threadIdx.x;
    int tx = tid & 15;
    int ty = tid >> 4;
    int row0 = blockIdx.x * BM;

    u64 acc[4][8];
#pragma unroll
    for (int i = 0; i < 4; i++)
#pragma unroll
        for (int j = 0; j < 8; j++) acc[i][j] = 0ull;

    for (int kb = 0; kb < FIN; kb += BK) {
#pragma unroll
        for (int i = 0; i < 2; i++) {
            int f = i * 256 + tid;
            int wr = f >> 5, wc4 = f & 31;
            *(float4*)&Ws[wr][wc4 * 4] =
                *(const float4*)&W[(kb + wr) * HC + wc4 * 4];
        }
#pragma unroll
        for (int i = 0; i < 2; i++) {
            int f = i * 256 + tid;
            int r = f >> 2, c4 = f & 3;
            float4 v = make_float4(0.f, 0.f, 0.f, 0.f);
            if (row0 + r < V)
                v = *(const float4*)&x[(size_t)(row0 + r) * FIN + kb + c4 * 4];
            xsT[c4 * 4 + 0][r] = v.x;
            xsT[c4 * 4 + 1][r] = v.y;
            xsT[c4 * 4 + 2][r] = v.z;
            xsT[c4 * 4 + 3][r] = v.w;
        }
        __syncthreads();

#pragma unroll
        for (int k = 0; k < BK; k++) {
            ulonglong2 xa = *(const ulonglong2*)&xsT[k][ty * 8];
            ulonglong2 xb = *(const ulonglong2*)&xsT[k][ty * 8 + 4];
            u64 xp[4] = {xa.x, xa.y, xb.x, xb.y};
            float4 w0 = *(const float4*)&Ws[k][tx * 8];
            float4 w1 = *(const float4*)&Ws[k][tx * 8 + 4];
            u64 wd[8] = {pack2(w0.x), pack2(w0.y), pack2(w0.z), pack2(w0.w),
                         pack2(w1.x), pack2(w1.y), pack2(w1.z), pack2(w1.w)};
#pragma unroll
            for (int i = 0; i < 4; i++)
#pragma unroll
                for (int j = 0; j < 8; j++)
                    ffma2(acc[i][j], xp[i], wd[j]);
        }
        __syncthreads();
    }

    float as[8], ad[8];
#pragma unroll
    for (int j = 0; j < 8; j++) {
        as[j] = __ldg(&a_src[tx * 8 + j]);
        ad[j] = __ldg(&a_dst[tx * 8 + j]);
    }

#pragma unroll
    for (int rp = 0; rp < 4; rp++) {
        float lo[8], hi[8];
#pragma unroll
        for (int j = 0; j < 8; j++) unpack2(acc[rp][j], lo[j], hi[j]);

#pragma unroll
        for (int half = 0; half < 2; half++) {
            float* rowv = half ? hi : lo;
            int r = row0 + ty * 8 + rp * 2 + half;
            float ps = 0.f, pd = 0.f;
#pragma unroll
            for (int j = 0; j < 8; j++) {
                ps += rowv[j] * as[j];
                pd += rowv[j] * ad[j];
            }
            ps += __shfl_xor_sync(0xffffffffu, ps, 1);
            pd += __shfl_xor_sync(0xffffffffu, pd, 1);
            ps += __shfl_xor_sync(0xffffffffu, ps, 2);
            pd += __shfl_xor_sync(0xffffffffu, pd, 2);

            if (r < V) {
                __half2 hp[4];
                hp[0] = __floats2half2_rn(rowv[0], rowv[1]);
                hp[1] = __floats2half2_rn(rowv[2], rowv[3]);
                hp[2] = __floats2half2_rn(rowv[4], rowv[5]);
                hp[3] = __floats2half2_rn(rowv[6], rowv[7]);
                *(uint4*)&g_z[(size_t)r * HC + tx * 8] = *(uint4*)hp;
                if ((tx & 3) == 0) {
                    int h = tx >> 2;
                    g_ssrc[r * 4 + h] = ps;
                    g_sdst[r * 4 + h] = pd;
                }
            }
        }
    }
}

// ======================================================================
// Aggregation: one warp per dst vertex, CSR walk.
// NO shuffles: every lane reads g_srcs[e] directly (same-address L1
// broadcast), computes w from a 1-sector ssrc gather, gathers 8B of
// fp16 z, accumulates via packed f32x2 FMA. den identical across the
// 8 lanes of a head -> no reduction needed. Fused normalize + ELU.
// ======================================================================
__global__ void agg_kernel(float* __restrict__ out, int V) {
    int d = (blockIdx.x * blockDim.x + threadIdx.x) >> 5;
    int lane = threadIdx.x & 31;
    if (d >= V) return;

    int beg = g_off[d], end = g_off[d + 1];
    int h = lane >> 3;
    float sd = g_sdst[d * 4 + h];

    u64 acc01 = 0ull, acc23 = 0ull;
    float den = 0.f;

    int e = beg;
    // unrolled-by-4 main loop: independent loads -> deep MLP
    for (; e + 4 <= end; e += 4) {
#pragma unroll
        for (int t = 0; t < 4; t++) {
            int s = __ldg(&g_srcs[e + t]);                    // broadcast
            float w = __expf(lrelu(__ldg(&g_ssrc[s * 4 + h]) + sd));
            den += w;
            u64 wp = pack2(w);
            uint2 raw = *(const uint2*)&g_z[(size_t)s * HC + lane * 4];
            float2 f0 = __half22float2(*(__half2*)&raw.x);
            float2 f1 = __half22float2(*(__half2*)&raw.y);
            ffma2(acc01, wp, pack2f(f0.x, f0.y));
            ffma2(acc23, wp, pack2f(f1.x, f1.y));
        }
    }
    for (; e < end; e++) {
        int s = __ldg(&g_srcs[e]);
        float w = __expf(lrelu(__ldg(&g_ssrc[s * 4 + h]) + sd));
        den += w;
        u64 wp = pack2(w);
        uint2 raw = *(const uint2*)&g_z[(size_t)s * HC + lane * 4];
        float2 f0 = __half22float2(*(__half2*)&raw.x);
        float2 f1 = __half22float2(*(__half2*)&raw.y);
        ffma2(acc01, wp, pack2f(f0.x, f0.y));
        ffma2(acc23, wp, pack2f(f1.x, f1.y));
    }

    float4 acc;
    unpack2(acc01, acc.x, acc.y);
    unpack2(acc23, acc.z, acc.w);

    float inv = 1.f / (den + 1e-9f);
    acc.x *= inv; acc.y *= inv; acc.z *= inv; acc.w *= inv;
    acc.x = acc.x > 0.f ? acc.x : expm1f(acc.x);
    acc.y = acc.y > 0.f ? acc.y : expm1f(acc.y);
    acc.z = acc.z > 0.f ? acc.z : expm1f(acc.z);
    acc.w = acc.w > 0.f ? acc.w : expm1f(acc.w);
    *(float4*)&out[(size_t)d * HC + lane * 4] = acc;
}

// ======================================================================
extern "C" void kernel_launch(void* const* d_in, const int* in_sizes, int n_in,
                              void* d_out, int out_size) {
    const float* x     = (const float*)d_in[0];
    const void*  ei    = d_in[1];
    const float* W     = (const float*)d_in[2];
    const float* a_src = (const float*)d_in[3];
    const float* a_dst = (const float*)d_in[4];
    float* out = (float*)d_out;

    int V = in_sizes[0] / FIN;
    int E = in_sizes[1] / 2;
    int nb = (V + SCAN_BLK - 1) / SCAN_BLK;

    // Side stream + fork/join events (created per call; kernel_launch only
    // runs a few times — eager + capture. No device memory involved.)
    cudaStream_t s1;
    cudaStreamCreateWithFlags(&s1, cudaStreamNonBlocking);
    cudaEvent_t ev_fork, ev_join;
    cudaEventCreateWithFlags(&ev_fork, cudaEventDisableTiming);
    cudaEventCreateWithFlags(&ev_join, cudaEventDisableTiming);

    // fork: side stream handles the entire edge/CSR pipeline
    cudaEventRecord(ev_fork, 0);
    cudaStreamWaitEvent(s1, ev_fork, 0);

    int scan_words = 2 * E;
    if (scan_words > 262144) scan_words = 262144;
    int dz_threads = (V > scan_words / 2) ? V : scan_words / 2;

    flag_reset_kernel<<<1, 32, 0, s1>>>();
    detect_zero_kernel<<<(dz_threads + 255) / 256, 256, 0, s1>>>(
        (const unsigned int*)ei, scan_words, V);
    hist_kernel<<<(E + 255) / 256, 256, 0, s1>>>(ei, E);
    scan_reduce_kernel<<<nb, SCAN_BLK, 0, s1>>>(V);
    scan_sums_kernel<<<1, 128, 0, s1>>>(nb);
    scan_final_kernel<<<nb, SCAN_BLK, 0, s1>>>(V);
    scatter_kernel<<<(E + 255) / 256, 256, 0, s1>>>(ei, E);

    // main stream: GEMM + attention scores (independent of edges)
    gemm_kernel<<<(V + BM - 1) / BM, 256>>>(x, W, a_src, a_dst, V);

    // join: agg needs both CSR and z/scores
    cudaEventRecord(ev_join, s1);
    cudaStreamWaitEvent(0, ev_join, 0);

    agg_kernel<<<(V + 7) / 8, 256>>>(out, V);
}

// round 8
// speedup vs baseline: 3.1255x; 1.1635x over previous
#include <cuda_runtime.h>
#include <cuda_bf16.h>
#include <cuda_fp16.h>
#include <mma.h>

using namespace nvcuda;

// Problem constants (GATLayer): V=100000, E=1600000, Fin=128, H=4, Cout=32
#define FIN   128
#define HC    128   // H*Cout
#define NHEAD 4
#define MAXV  100000
#define MAXE  1600000
#define SCAN_BLK 1024

// -------- scratch (static device globals; allocation-free rule) --------
__device__ __align__(16) __half g_z[MAXV * HC];       // 25.6 MB (fp16 z)
__device__ __align__(16) float g_ssrc[MAXV * NHEAD];
__device__ __align__(16) float g_sdst[MAXV * NHEAD];
__device__ int g_deg[MAXV];
__device__ int g_off[MAXV + 1];
__device__ int g_cur[MAXV];
__device__ int g_bsum[256];
__device__ int g_srcs[MAXE];
__device__ int g_is32;

// -------- helpers --------
__device__ __forceinline__ float lrelu(float v) {
    return fmaxf(v, 0.2f * v);   // branchless LeakyReLU(0.2)
}

typedef unsigned long long u64;
__device__ __forceinline__ void ffma2(u64& d, u64 a, u64 b) {
    asm("fma.rn.f32x2 %0, %1, %2, %0;" : "+l"(d) : "l"(a), "l"(b));
}
__device__ __forceinline__ u64 pack2(float x) {
    u64 r; asm("mov.b64 %0, {%1, %1};" : "=l"(r) : "f"(x)); return r;
}
__device__ __forceinline__ u64 pack2f(float lo, float hi) {
    u64 r; asm("mov.b64 %0, {%1, %2};" : "=l"(r) : "f"(lo), "f"(hi)); return r;
}
__device__ __forceinline__ void unpack2(u64 p, float& lo, float& hi) {
    asm("mov.b64 {%0, %1}, %2;" : "=f"(lo), "=f"(hi) : "l"(p));
}

// ======================================================================
// probe + deg-zero (fused): int64 edge_index has all odd 32-bit words 0
// ======================================================================
__global__ void flag_reset_kernel() {
    if (threadIdx.x == 0) g_is32 = 0;
}

__global__ void detect_zero_kernel(const unsigned int* __restrict__ w,
                                   int n_words, int V) {
    int i = blockIdx.x * blockDim.x + threadIdx.x;
    int j = 2 * i + 1;
    if (j < n_words && w[j] != 0u) g_is32 = 1;
    if (i < V) g_deg[i] = 0;
}

// ======================================================================
// CSR build
// ======================================================================
__global__ void hist_kernel(const void* __restrict__ ei, int E) {
    int e = blockIdx.x * blockDim.x + threadIdx.x;
    if (e >= E) return;
    int dst;
    if (g_is32) dst = ((const int*)ei)[E + e];
    else        dst = (int)((const long long*)ei)[(long long)E + e];
    atomicAdd(&g_deg[dst], 1);
}

__global__ void scan_reduce_kernel(int V) {
    __shared__ int sh[SCAN_BLK];
    int t = threadIdx.x;
    int v = blockIdx.x * SCAN_BLK + t;
    sh[t] = (v < V) ? g_deg[v] : 0;
    __syncthreads();
#pragma unroll
    for (int s = SCAN_BLK / 2; s > 0; s >>= 1) {
        if (t < s) sh[t] += sh[t + s];
        __syncthreads();
    }
    if (t == 0) g_bsum[blockIdx.x] = sh[0];
}

__global__ void scan_sums_kernel(int nb) {
    __shared__ int sh[128];
    int t = threadIdx.x;
    int x = (t < nb) ? g_bsum[t] : 0;
    sh[t] = x;
    __syncthreads();
#pragma unroll
    for (int off = 1; off < 128; off <<= 1) {
        int v = (t >= off) ? sh[t - off] : 0;
        __syncthreads();
        sh[t] += v;
        __syncthreads();
    }
    if (t < nb) g_bsum[t] = sh[t] - x;   // exclusive
}

__global__ void scan_final_kernel(int V) {
    __shared__ int sh[SCAN_BLK];
    int t = threadIdx.x;
    int v = blockIdx.x * SCAN_BLK + t;
    int x = (v < V) ? g_deg[v] : 0;
    sh[t] = x;
    __syncthreads();
#pragma unroll
    for (int off = 1; off < SCAN_BLK; off <<= 1) {
        int u = (t >= off) ? sh[t - off] : 0;
        __syncthreads();
        sh[t] += u;
        __syncthreads();
    }
    int excl = sh[t] - x + g_bsum[blockIdx.x];
    if (v < V) {
        g_off[v] = excl;
        g_cur[v] = excl;
        if (v == V - 1) g_off[V] = excl + x;
    }
}

__global__ void scatter_kernel(const void* __restrict__ ei, int E) {
    int e = blockIdx.x * blockDim.x + threadIdx.x;
    if (e >= E) return;
    int src, dst;
    if (g_is32) {
        const int* p = (const int*)ei;
        src = p[e]; dst = p[E + e];
    } else {
        const long long* p = (const long long*)ei;
        src = (int)p[e]; dst = (int)p[(long long)E + e];
    }
    int pos = atomicAdd(&g_cur[dst], 1);
    g_srcs[pos] = src;
}

// ======================================================================
// GEMM: z = x @ W via fp16 tensor cores (HMMA, fp32 accumulate).
// BM=64, BN=128(full), BK=16, 256 threads = 8 warps.
// Warp w = (wr=w>>2, wc=w&3) computes rows [wr*32,+32) x cols [wc*32,+32)
// as 2x2 wmma 16x16x16 frags. Epilogue: frags -> per-warp smem scratch,
// per-lane row read -> head score (warp col block == one head) + fp16 z.
// ======================================================================
#define BM 64
#define BK 16
#define XPAD 8
#define WPAD 8
#define SLD 36   // scratch row stride (mult of 4 floats = 16B, 4-way bank)

__global__ void __launch_bounds__(256, 1)
gemm_kernel(const float* __restrict__ x,
            const float* __restrict__ W,
            const float* __restrict__ a_src,
            const float* __restrict__ a_dst, int V) {
    __shared__ __align__(16) __half xs[BM][BK + XPAD];     // 3 KB
    __shared__ __align__(16) __half Wsm[BK][HC + WPAD];    // 4.25 KB
    __shared__ __align__(16) float scratch[8][32][SLD];    // 36 KB

    int tid = threadIdx.x;
    int wid = tid >> 5, lane = tid & 31;
    int wr = wid >> 2, wc = wid & 3;
    int row0 = blockIdx.x * BM;

    wmma::fragment<wmma::accumulator, 16, 16, 16, float> cf[2][2];
#pragma unroll
    for (int i = 0; i < 2; i++)
#pragma unroll
        for (int j = 0; j < 2; j++) wmma::fill_fragment(cf[i][j], 0.f);

    for (int kb = 0; kb < FIN; kb += BK) {
        // xs: 64x16 fp32 -> half. 256 float4 loads, 1 per thread.
        {
            int r = tid >> 2, c4 = tid & 3;
            float4 v = make_float4(0.f, 0.f, 0.f, 0.f);
            if (row0 + r < V)
                v = *(const float4*)&x[(size_t)(row0 + r) * FIN + kb + c4 * 4];
            __half2* dp = (__half2*)&xs[r][c4 * 4];
            dp[0] = __floats2half2_rn(v.x, v.y);
            dp[1] = __floats2half2_rn(v.z, v.w);
        }
        // Wsm: 16x128 fp32 -> half. 512 float4 loads, 2 per thread.
#pragma unroll
        for (int i = 0; i < 2; i++) {
            int f = i * 256 + tid;
            int r = f >> 5, c4 = f & 31;
            float4 v = *(const float4*)&W[(kb + r) * HC + c4 * 4];
            __half2* dp = (__half2*)&Wsm[r][c4 * 4];
            dp[0] = __floats2half2_rn(v.x, v.y);
            dp[1] = __floats2half2_rn(v.z, v.w);
        }
        __syncthreads();

        wmma::fragment<wmma::matrix_a, 16, 16, 16, __half, wmma::row_major> af[2];
        wmma::fragment<wmma::matrix_b, 16, 16, 16, __half, wmma::row_major> bf[2];
#pragma unroll
        for (int i = 0; i < 2; i++)
            wmma::load_matrix_sync(af[i], &xs[wr * 32 + i * 16][0], BK + XPAD);
#pragma unroll
        for (int j = 0; j < 2; j++)
            wmma::load_matrix_sync(bf[j], &Wsm[0][wc * 32 + j * 16], HC + WPAD);
#pragma unroll
        for (int i = 0; i < 2; i++)
#pragma unroll
            for (int j = 0; j < 2; j++)
                wmma::mma_sync(cf[i][j], af[i], bf[j], cf[i][j]);
        __syncthreads();
    }

    // epilogue: frags -> scratch, then per-lane row processing
#pragma unroll
    for (int i = 0; i < 2; i++)
#pragma unroll
        for (int j = 0; j < 2; j++)
            wmma::store_matrix_sync(&scratch[wid][i * 16][j * 16], cf[i][j],
                                    SLD, wmma::mem_row_major);
    __syncwarp();

    int h = wc;                       // this warp's col block == head h
    int r = row0 + wr * 32 + lane;    // global row

    float vals[32];
#pragma unroll
    for (int q = 0; q < 8; q++) {
        float4 v = *(float4*)&scratch[wid][lane][q * 4];
        vals[q * 4 + 0] = v.x; vals[q * 4 + 1] = v.y;
        vals[q * 4 + 2] = v.z; vals[q * 4 + 3] = v.w;
    }
    float ps = 0.f, pd = 0.f;
#pragma unroll
    for (int c = 0; c < 32; c++) {
        ps += vals[c] * __ldg(&a_src[h * 32 + c]);
        pd += vals[c] * __ldg(&a_dst[h * 32 + c]);
    }

    if (r < V) {
        __half2 hp[16];
#pragma unroll
        for (int q = 0; q < 16; q++)
            hp[q] = __floats2half2_rn(vals[2 * q], vals[2 * q + 1]);
        uint4* dst = (uint4*)&g_z[(size_t)r * HC + wc * 32];
#pragma unroll
        for (int q = 0; q < 4; q++) dst[q] = ((uint4*)hp)[q];
        g_ssrc[r * 4 + h] = ps;
        g_sdst[r * 4 + h] = pd;
    }
}

// ======================================================================
// Aggregation: one warp per dst vertex, CSR walk, broadcast srcs loads,
// fp16 z gather (256B/warp/edge), packed f32x2 accumulate, fused
// softmax-normalize + ELU. (At L1tex-wavefront/L2 floor — unchanged.)
// ======================================================================
__global__ void agg_kernel(float* __restrict__ out, int V) {
    int d = (blockIdx.x * blockDim.x + threadIdx.x) >> 5;
    int lane = threadIdx.x & 31;
    if (d >= V) return;

    int beg = g_off[d], end = g_off[d + 1];
    int h = lane >> 3;
    float sd = g_sdst[d * 4 + h];

    u64 acc01 = 0ull, acc23 = 0ull;
    float den = 0.f;

    int e = beg;
    for (; e + 4 <= end; e += 4) {
#pragma unroll
        for (int t = 0; t < 4; t++) {
            int s = __ldg(&g_srcs[e + t]);                    // broadcast
            float w = __expf(lrelu(__ldg(&g_ssrc[s * 4 + h]) + sd));
            den += w;
            u64 wp = pack2(w);
            uint2 raw = *(const uint2*)&g_z[(size_t)s * HC + lane * 4];
            float2 f0 = __half22float2(*(__half2*)&raw.x);
            float2 f1 = __half22float2(*(__half2*)&raw.y);
            ffma2(acc01, wp, pack2f(f0.x, f0.y));
            ffma2(acc23, wp, pack2f(f1.x, f1.y));
        }
    }
    for (; e < end; e++) {
        int s = __ldg(&g_srcs[e]);
        float w = __expf(lrelu(__ldg(&g_ssrc[s * 4 + h]) + sd));
        den += w;
        u64 wp = pack2(w);
        uint2 raw = *(const uint2*)&g_z[(size_t)s * HC + lane * 4];
        float2 f0 = __half22float2(*(__half2*)&raw.x);
        float2 f1 = __half22float2(*(__half2*)&raw.y);
        ffma2(acc01, wp, pack2f(f0.x, f0.y));
        ffma2(acc23, wp, pack2f(f1.x, f1.y));
    }

    float4 acc;
    unpack2(acc01, acc.x, acc.y);
    unpack2(acc23, acc.z, acc.w);

    float inv = 1.f / (den + 1e-9f);
    acc.x *= inv; acc.y *= inv; acc.z *= inv; acc.w *= inv;
    acc.x = acc.x > 0.f ? acc.x : expm1f(acc.x);
    acc.y = acc.y > 0.f ? acc.y : expm1f(acc.y);
    acc.z = acc.z > 0.f ? acc.z : expm1f(acc.z);
    acc.w = acc.w > 0.f ? acc.w : expm1f(acc.w);
    *(float4*)&out[(size_t)d * HC + lane * 4] = acc;
}

// ======================================================================
extern "C" void kernel_launch(void* const* d_in, const int* in_sizes, int n_in,
                              void* d_out, int out_size) {
    const float* x     = (const float*)d_in[0];
    const void*  ei    = d_in[1];
    const float* W     = (const float*)d_in[2];
    const float* a_src = (const float*)d_in[3];
    const float* a_dst = (const float*)d_in[4];
    float* out = (float*)d_out;

    int V = in_sizes[0] / FIN;
    int E = in_sizes[1] / 2;
    int nb = (V + SCAN_BLK - 1) / SCAN_BLK;

    // Side stream + fork/join events (created per call; kernel_launch only
    // runs a few times — eager + capture. No device memory involved.)
    cudaStream_t s1;
    cudaStreamCreateWithFlags(&s1, cudaStreamNonBlocking);
    cudaEvent_t ev_fork, ev_join;
    cudaEventCreateWithFlags(&ev_fork, cudaEventDisableTiming);
    cudaEventCreateWithFlags(&ev_join, cudaEventDisableTiming);

    // fork: side stream handles the entire edge/CSR pipeline
    cudaEventRecord(ev_fork, 0);
    cudaStreamWaitEvent(s1, ev_fork, 0);

    int scan_words = 2 * E;
    if (scan_words > 262144) scan_words = 262144;
    int dz_threads = (V > scan_words / 2) ? V : scan_words / 2;

    flag_reset_kernel<<<1, 32, 0, s1>>>();
    detect_zero_kernel<<<(dz_threads + 255) / 256, 256, 0, s1>>>(
        (const unsigned int*)ei, scan_words, V);
    hist_kernel<<<(E + 255) / 256, 256, 0, s1>>>(ei, E);
    scan_reduce_kernel<<<nb, SCAN_BLK, 0, s1>>>(V);
    scan_sums_kernel<<<1, 128, 0, s1>>>(nb);
    scan_final_kernel<<<nb, SCAN_BLK, 0, s1>>>(V);
    scatter_kernel<<<(E + 255) / 256, 256, 0, s1>>>(ei, E);

    // main stream: tensor-core GEMM + attention scores
    gemm_kernel<<<(V + BM - 1) / BM, 256>>>(x, W, a_src, a_dst, V);

    // join: agg needs both CSR and z/scores
    cudaEventRecord(ev_join, s1);
    cudaStreamWaitEvent(0, ev_join, 0);

    agg_kernel<<<(V + 7) / 8, 256>>>(out, V);
}